// round 2
// baseline (speedup 1.0000x reference)
#include <cuda_runtime.h>
#include <cuda_bf16.h>
#include <cstdint>

#define N_NODES 100000
#define N_EDGES 1600000
#define D 64
#define N_GRAPHS 16
#define N_CLASSES 6
#define BN_EPS 1e-5f

// ---------------- device scratch (no allocation allowed) ----------------
__device__ __align__(16) float g_h[2][N_NODES * D];     // ping-pong layer buffers
__device__ __align__(16) float g_agg[N_NODES * D];      // edge aggregation buffer
__device__ float g_pool[N_GRAPHS * D];                  // per-graph sums
__device__ float g_cnt[N_GRAPHS];                       // per-graph counts

// ---------------- zero init (agg + pool) ----------------
__global__ void zero_kernel() {
    int i = blockIdx.x * blockDim.x + threadIdx.x;
    int stride = gridDim.x * blockDim.x;
    float4 z4 = make_float4(0.f, 0.f, 0.f, 0.f);
    float4* a4 = reinterpret_cast<float4*>(g_agg);
    for (int idx = i; idx < N_NODES * (D / 4); idx += stride) a4[idx] = z4;
    if (i < N_GRAPHS * D) g_pool[i] = 0.f;
    if (i < N_GRAPHS) g_cnt[i] = 0.f;
}

// ---------------- edge scatter: agg[dst] += h[src] ----------------
// thread t -> edge e = t>>4, float4 chunk c = t&15. Vector red (v4.f32)
// cuts REDG lane-ops 4x; h (25.6MB) fits in L2 so both sides are L2 traffic.
// Indices are INT32 (JAX x64-disabled downcasts the requested int64).
__global__ __launch_bounds__(256) void scatter_kernel(
    const int* __restrict__ ei, const float* __restrict__ x, int in_sel)
{
    const float* __restrict__ h = (in_sel < 0) ? x : g_h[in_sel];
    unsigned t = blockIdx.x * 256u + threadIdx.x;
    if (t >= (unsigned)N_EDGES * 16u) return;
    unsigned e = t >> 4;
    unsigned c = t & 15u;
    unsigned s = (unsigned)__ldg(ei + e);
    unsigned d = (unsigned)__ldg(ei + N_EDGES + e);
    if (s >= (unsigned)N_NODES || d >= (unsigned)N_NODES) return;  // safety
    float4 v = __ldg(reinterpret_cast<const float4*>(h) + (size_t)s * 16 + c);
    float* p = g_agg + (size_t)d * D + c * 4;
    asm volatile("red.global.add.v4.f32 [%0], {%1,%2,%3,%4};"
                 :: "l"(p), "f"(v.x), "f"(v.y), "f"(v.z), "f"(v.w)
                 : "memory");
}

// ---------------- fused node update ----------------
// z = h + agg;  y = relu(bn1(z@W1+b1));  h' = relu(bn2(y@W2+b2))
// One thread per node; z/y live in registers (fully unrolled k-loops),
// W1/W2 staged in static shared (warp-broadcast LDS.128). BN folded to
// scale/shift. Also zeroes g_agg behind itself for the next layer.
#define NPB 128

__global__ __launch_bounds__(NPB) void node_kernel(
    const float* __restrict__ x, int in_sel, int out_sel, int layer,
    const float* __restrict__ W1, const float* __restrict__ b1,
    const float* __restrict__ g1, const float* __restrict__ be1,
    const float* __restrict__ m1, const float* __restrict__ v1,
    const float* __restrict__ W2, const float* __restrict__ b2,
    const float* __restrict__ g2, const float* __restrict__ be2,
    const float* __restrict__ m2, const float* __restrict__ v2)
{
    __shared__ __align__(16) float Ws1[D * D];
    __shared__ __align__(16) float Ws2[D * D];
    __shared__ float sc1[D], sh1[D], sc2[D], sh2[D];

    const int tid = threadIdx.x;
    const float* __restrict__ hin = (in_sel < 0) ? x : g_h[in_sel];
    float* __restrict__ hout = g_h[out_sel];

    // stage weights + folded BN params
    const float* w1 = W1 + layer * D * D;
    const float* w2 = W2 + layer * D * D;
    #pragma unroll
    for (int i = tid; i < D * D; i += NPB) {
        Ws1[i] = __ldg(w1 + i);
        Ws2[i] = __ldg(w2 + i);
    }
    if (tid < D) {
        int o = layer * D + tid;
        float s1 = __ldg(g1 + o) * rsqrtf(__ldg(v1 + o) + BN_EPS);
        sc1[tid] = s1;
        sh1[tid] = (__ldg(b1 + o) - __ldg(m1 + o)) * s1 + __ldg(be1 + o);
        float s2 = __ldg(g2 + o) * rsqrtf(__ldg(v2 + o) + BN_EPS);
        sc2[tid] = s2;
        sh2[tid] = (__ldg(b2 + o) - __ldg(m2 + o)) * s2 + __ldg(be2 + o);
    }

    const int node = blockIdx.x * NPB + tid;
    const bool act = (node < N_NODES);

    float z[D];
    if (act) {
        const float4* hp = reinterpret_cast<const float4*>(hin + (size_t)node * D);
        float4* ap = reinterpret_cast<float4*>(g_agg + (size_t)node * D);
        float4 z4 = make_float4(0.f, 0.f, 0.f, 0.f);
        #pragma unroll
        for (int c = 0; c < D / 4; ++c) {
            float4 a = __ldg(hp + c);
            float4 b = ap[c];
            z[c * 4 + 0] = a.x + b.x;
            z[c * 4 + 1] = a.y + b.y;
            z[c * 4 + 2] = a.z + b.z;
            z[c * 4 + 3] = a.w + b.w;
            ap[c] = z4;  // zero agg for next layer
        }
    }
    __syncthreads();

    if (act) {
        float y[D];
        // GEMM1 + BN1 + ReLU
        #pragma unroll
        for (int jg = 0; jg < 8; ++jg) {
            float acc[8];
            #pragma unroll
            for (int jj = 0; jj < 8; ++jj) acc[jj] = 0.f;
            #pragma unroll
            for (int k = 0; k < D; ++k) {
                float zk = z[k];
                float4 wa = *reinterpret_cast<const float4*>(Ws1 + k * D + jg * 8);
                float4 wb = *reinterpret_cast<const float4*>(Ws1 + k * D + jg * 8 + 4);
                acc[0] = fmaf(zk, wa.x, acc[0]);
                acc[1] = fmaf(zk, wa.y, acc[1]);
                acc[2] = fmaf(zk, wa.z, acc[2]);
                acc[3] = fmaf(zk, wa.w, acc[3]);
                acc[4] = fmaf(zk, wb.x, acc[4]);
                acc[5] = fmaf(zk, wb.y, acc[5]);
                acc[6] = fmaf(zk, wb.z, acc[6]);
                acc[7] = fmaf(zk, wb.w, acc[7]);
            }
            #pragma unroll
            for (int jj = 0; jj < 8; ++jj) {
                int j = jg * 8 + jj;
                y[j] = fmaxf(fmaf(acc[jj], sc1[j], sh1[j]), 0.f);
            }
        }

        // GEMM2 + BN2 + ReLU -> hout
        float4* op = reinterpret_cast<float4*>(hout + (size_t)node * D);
        #pragma unroll
        for (int jg = 0; jg < 8; ++jg) {
            float acc[8];
            #pragma unroll
            for (int jj = 0; jj < 8; ++jj) acc[jj] = 0.f;
            #pragma unroll
            for (int k = 0; k < D; ++k) {
                float yk = y[k];
                float4 wa = *reinterpret_cast<const float4*>(Ws2 + k * D + jg * 8);
                float4 wb = *reinterpret_cast<const float4*>(Ws2 + k * D + jg * 8 + 4);
                acc[0] = fmaf(yk, wa.x, acc[0]);
                acc[1] = fmaf(yk, wa.y, acc[1]);
                acc[2] = fmaf(yk, wa.z, acc[2]);
                acc[3] = fmaf(yk, wa.w, acc[3]);
                acc[4] = fmaf(yk, wb.x, acc[4]);
                acc[5] = fmaf(yk, wb.y, acc[5]);
                acc[6] = fmaf(yk, wb.z, acc[6]);
                acc[7] = fmaf(yk, wb.w, acc[7]);
            }
            float r[8];
            #pragma unroll
            for (int jj = 0; jj < 8; ++jj) {
                int j = jg * 8 + jj;
                r[jj] = fmaxf(fmaf(acc[jj], sc2[j], sh2[j]), 0.f);
            }
            op[jg * 2 + 0] = make_float4(r[0], r[1], r[2], r[3]);
            op[jg * 2 + 1] = make_float4(r[4], r[5], r[6], r[7]);
        }
    }
}

// ---------------- global mean pool (batch is sorted int32) ----------------
// 4 node-rows x 64 dims per block; register run-length accumulate,
// one atomic per (segment boundary, dim).
#define POOL_BLOCKS 256
__global__ __launch_bounds__(256) void pool_kernel(const int* __restrict__ batch, int sel) {
    const float* __restrict__ h = g_h[sel];
    int d = threadIdx.x & 63;
    int row = blockIdx.x * 4 + (threadIdx.x >> 6);
    int total_rows = POOL_BLOCKS * 4;
    int chunk = (N_NODES + total_rows - 1) / total_rows;
    int start = row * chunk;
    int end = min(start + chunk, N_NODES);
    if (start >= end) return;
    int cur = __ldg(batch + start);
    float acc = 0.f, cnt = 0.f;
    for (int n = start; n < end; ++n) {
        int b = __ldg(batch + n);
        if (b != cur) {
            if ((unsigned)cur < N_GRAPHS) {
                atomicAdd(&g_pool[cur * D + d], acc);
                if (d == 0) atomicAdd(&g_cnt[cur], cnt);
            }
            acc = 0.f; cnt = 0.f; cur = b;
        }
        acc += __ldg(h + (size_t)n * D + d);
        cnt += 1.f;
    }
    if ((unsigned)cur < N_GRAPHS) {
        atomicAdd(&g_pool[cur * D + d], acc);
        if (d == 0) atomicAdd(&g_cnt[cur], cnt);
    }
}

// ---------------- heads: out = [primary(16x6), secondary(16x6)] ----------------
__global__ void head_kernel(const float* __restrict__ wp, const float* __restrict__ bp,
                            const float* __restrict__ ws, const float* __restrict__ bs,
                            float* __restrict__ out) {
    int t = threadIdx.x;
    if (t >= N_GRAPHS * N_CLASSES) return;
    int g = t / N_CLASSES, c = t % N_CLASSES;
    float inv = 1.f / fmaxf(g_cnt[g], 1.f);
    float accP = 0.f, accS = 0.f;
    #pragma unroll
    for (int d = 0; d < D; ++d) {
        float p = g_pool[g * D + d] * inv;
        accP = fmaf(p, wp[d * N_CLASSES + c], accP);
        accS = fmaf(p, ws[d * N_CLASSES + c], accS);
    }
    out[g * N_CLASSES + c] = accP + bp[c];
    out[N_GRAPHS * N_CLASSES + g * N_CLASSES + c] = accS + bs[c];
}

// ---------------- launch ----------------
extern "C" void kernel_launch(void* const* d_in, const int* in_sizes, int n_in,
                              void* d_out, int out_size) {
    const float* x   = (const float*)d_in[0];
    const int*   ei  = (const int*)d_in[1];    // int32 (JAX x64 disabled)
    const int*   bat = (const int*)d_in[2];    // int32
    const float* W1  = (const float*)d_in[3];
    const float* b1  = (const float*)d_in[4];
    const float* g1  = (const float*)d_in[5];
    const float* be1 = (const float*)d_in[6];
    const float* m1  = (const float*)d_in[7];
    const float* v1  = (const float*)d_in[8];
    const float* W2  = (const float*)d_in[9];
    const float* b2  = (const float*)d_in[10];
    const float* g2  = (const float*)d_in[11];
    const float* be2 = (const float*)d_in[12];
    const float* m2  = (const float*)d_in[13];
    const float* v2  = (const float*)d_in[14];
    const float* wp  = (const float*)d_in[15];
    const float* bp  = (const float*)d_in[16];
    const float* ws  = (const float*)d_in[17];
    const float* bs  = (const float*)d_in[18];
    float* out = (float*)d_out;

    zero_kernel<<<2048, 256>>>();

    const int scatter_grid = (int)(((long long)N_EDGES * 16 + 255) / 256);
    const int node_grid = (N_NODES + NPB - 1) / NPB;

    // layer 0: x -> g_h[0]
    scatter_kernel<<<scatter_grid, 256>>>(ei, x, -1);
    node_kernel<<<node_grid, NPB>>>(x, -1, 0, 0,
        W1, b1, g1, be1, m1, v1, W2, b2, g2, be2, m2, v2);
    // layer 1: g_h[0] -> g_h[1]
    scatter_kernel<<<scatter_grid, 256>>>(ei, x, 0);
    node_kernel<<<node_grid, NPB>>>(x, 0, 1, 1,
        W1, b1, g1, be1, m1, v1, W2, b2, g2, be2, m2, v2);
    // layer 2: g_h[1] -> g_h[0]
    scatter_kernel<<<scatter_grid, 256>>>(ei, x, 1);
    node_kernel<<<node_grid, NPB>>>(x, 1, 0, 2,
        W1, b1, g1, be1, m1, v1, W2, b2, g2, be2, m2, v2);

    pool_kernel<<<POOL_BLOCKS, 256>>>(bat, 0);
    head_kernel<<<1, 128>>>(wp, bp, ws, bs, out);
}

// round 3
// speedup vs baseline: 1.3529x; 1.3529x over previous
#include <cuda_runtime.h>
#include <cuda_bf16.h>
#include <cstdint>

#define N_NODES 100000
#define N_EDGES 1600000
#define D 64
#define N_GRAPHS 16
#define N_CLASSES 6
#define BN_EPS 1e-5f

// ---------------- device scratch (no allocation allowed) ----------------
__device__ __align__(16) float g_h[2][N_NODES * D];   // ping-pong layer buffers
__device__ int g_deg[N_NODES];                        // in-degree histogram
__device__ int g_off[N_NODES + 1];                    // CSR offsets (by dst)
__device__ int g_cur[N_NODES];                        // placement cursors
__device__ int g_srcs[N_EDGES];                       // src ids grouped by dst
__device__ float g_pool[N_GRAPHS * D];                // per-graph sums
__device__ float g_cnt[N_GRAPHS];                     // per-graph counts

// ---------------- prep: zero small buffers ----------------
__global__ void prep_kernel() {
    int i = blockIdx.x * blockDim.x + threadIdx.x;
    int stride = gridDim.x * blockDim.x;
    for (int n = i; n < N_NODES; n += stride) { g_deg[n] = 0; g_cur[n] = 0; }
    if (i < N_GRAPHS * D) g_pool[i] = 0.f;
    if (i < N_GRAPHS) g_cnt[i] = 0.f;
}

// ---------------- CSR build: histogram of dst ----------------
__global__ __launch_bounds__(256) void hist_kernel(const int* __restrict__ ei) {
    int e = blockIdx.x * 256 + threadIdx.x;
    if (e >= N_EDGES) return;
    unsigned d = (unsigned)__ldg(ei + N_EDGES + e);
    if (d < (unsigned)N_NODES) atomicAdd(&g_deg[d], 1);
}

// ---------------- CSR build: exclusive scan (single block) ----------------
__global__ __launch_bounds__(1024) void scan_kernel() {
    __shared__ int part[1024];
    const int tid = threadIdx.x;
    const int CH = (N_NODES + 1023) / 1024;  // 98
    int s = tid * CH, e = min(s + CH, N_NODES);
    int sum = 0;
    for (int n = s; n < e; ++n) sum += g_deg[n];
    part[tid] = sum;
    __syncthreads();
    // Hillis-Steele inclusive scan
    for (int o = 1; o < 1024; o <<= 1) {
        int v = (tid >= o) ? part[tid - o] : 0;
        __syncthreads();
        part[tid] += v;
        __syncthreads();
    }
    int run = (tid > 0) ? part[tid - 1] : 0;  // exclusive base
    for (int n = s; n < e; ++n) { g_off[n] = run; run += g_deg[n]; }
    if (tid == 1023) g_off[N_NODES] = run;
}

// ---------------- CSR build: place src ids grouped by dst ----------------
__global__ __launch_bounds__(256) void place_kernel(const int* __restrict__ ei) {
    int e = blockIdx.x * 256 + threadIdx.x;
    if (e >= N_EDGES) return;
    unsigned s = (unsigned)__ldg(ei + e);
    unsigned d = (unsigned)__ldg(ei + N_EDGES + e);
    if (s >= (unsigned)N_NODES || d >= (unsigned)N_NODES) return;
    int pos = g_off[d] + atomicAdd(&g_cur[d], 1);
    g_srcs[pos] = (int)s;
}

// ---------------- fused layer: gather + MLP(2x GEMM + BN + ReLU) ----------------
// Block = 128 nodes, 256 threads.
//   Phase G: z[n] = h[n] + sum_{s in N(n)} h[s], staged transposed in smem
//            zt[k][node] (16 consecutive threads read one 256B src row).
//   Phase 1: GEMM1 (register tile 8 nodes x 4 outs, 3 LDS.128 / 32 FFMA),
//            BN1-fold + ReLU, y written back transposed into zt.
//   Phase 2: W2 swapped into Wb, GEMM2, BN2-fold + ReLU, coalesced STG.128.
#define NPB 128
#define ZT_LD 132
#define LAYER_SMEM_FLOATS (D * ZT_LD + D * D + 4 * D)  // 8448+4096+256 = 12800

__global__ __launch_bounds__(256, 3) void layer_kernel(
    const float* __restrict__ x, int in_sel, int out_sel, int layer,
    const float* __restrict__ W1, const float* __restrict__ b1,
    const float* __restrict__ g1, const float* __restrict__ be1,
    const float* __restrict__ m1, const float* __restrict__ v1,
    const float* __restrict__ W2, const float* __restrict__ b2,
    const float* __restrict__ g2, const float* __restrict__ be2,
    const float* __restrict__ m2, const float* __restrict__ v2)
{
    extern __shared__ float smem[];
    float* zt  = smem;                    // [64][132]
    float* Wb  = smem + D * ZT_LD;        // [64][64]
    float* sc1 = Wb + D * D;
    float* sh1 = sc1 + D;
    float* sc2 = sh1 + D;
    float* sh2 = sc2 + D;

    const int tid = threadIdx.x;
    const int node0 = blockIdx.x * NPB;
    const float* __restrict__ hin = (in_sel < 0) ? x : g_h[in_sel];
    float* __restrict__ hout = g_h[out_sel];
    const float4* __restrict__ h4 = reinterpret_cast<const float4*>(hin);

    // stage W1 + folded BN params
    const float* w1 = W1 + layer * D * D;
    #pragma unroll
    for (int i = tid; i < D * D; i += 256) Wb[i] = __ldg(w1 + i);
    if (tid < D) {
        int o = layer * D + tid;
        float s1 = __ldg(g1 + o) * rsqrtf(__ldg(v1 + o) + BN_EPS);
        sc1[tid] = s1;
        sh1[tid] = (__ldg(b1 + o) - __ldg(m1 + o)) * s1 + __ldg(be1 + o);
        float s2 = __ldg(g2 + o) * rsqrtf(__ldg(v2 + o) + BN_EPS);
        sc2[tid] = s2;
        sh2[tid] = (__ldg(b2 + o) - __ldg(m2 + o)) * s2 + __ldg(be2 + o);
    }

    // ---- Phase G: gather. task = (local node, float4 chunk) ----
    #pragma unroll
    for (int it = 0; it < (NPB * 16) / 256; ++it) {
        int task = tid + it * 256;
        int nl = task >> 4;           // local node 0..127
        int c  = task & 15;           // chunk 0..15
        int n  = node0 + nl;
        if (n < N_NODES) {
            float4 acc = __ldg(h4 + (size_t)n * 16 + c);   // self term
            int eb = __ldg(&g_off[n]);
            int ee = __ldg(&g_off[n + 1]);
            #pragma unroll 2
            for (int e = eb; e < ee; ++e) {
                int s = __ldg(&g_srcs[e]);
                float4 v = __ldg(h4 + (size_t)s * 16 + c);
                acc.x += v.x; acc.y += v.y; acc.z += v.z; acc.w += v.w;
            }
            int k = c * 4;
            zt[(k + 0) * ZT_LD + nl] = acc.x;
            zt[(k + 1) * ZT_LD + nl] = acc.y;
            zt[(k + 2) * ZT_LD + nl] = acc.z;
            zt[(k + 3) * ZT_LD + nl] = acc.w;
        }
    }
    __syncthreads();

    // ---- GEMM thread tile: 8 nodes x 4 outs ----
    const int tj = tid & 15;          // out group  (j0 = 4*tj)
    const int tn = tid >> 4;          // node group (n0 = 8*tn)
    const int j0 = tj * 4;
    const int n0 = tn * 8;

    float acc[8][4];
    #pragma unroll
    for (int i = 0; i < 8; ++i)
        #pragma unroll
        for (int j = 0; j < 4; ++j) acc[i][j] = 0.f;

    // ---- Phase 1: z @ W1 ----
    #pragma unroll 4
    for (int k = 0; k < D; ++k) {
        float4 za = *reinterpret_cast<const float4*>(zt + k * ZT_LD + n0);
        float4 zb = *reinterpret_cast<const float4*>(zt + k * ZT_LD + n0 + 4);
        float4 w  = *reinterpret_cast<const float4*>(Wb + k * D + j0);
        float zr[8] = {za.x, za.y, za.z, za.w, zb.x, zb.y, zb.z, zb.w};
        #pragma unroll
        for (int i = 0; i < 8; ++i) {
            acc[i][0] = fmaf(zr[i], w.x, acc[i][0]);
            acc[i][1] = fmaf(zr[i], w.y, acc[i][1]);
            acc[i][2] = fmaf(zr[i], w.z, acc[i][2]);
            acc[i][3] = fmaf(zr[i], w.w, acc[i][3]);
        }
    }
    __syncthreads();   // all zt/Wb reads of GEMM1 done

    // BN1 + ReLU, write y back transposed into zt; swap W2 into Wb
    {
        float s[4] = {sc1[j0], sc1[j0 + 1], sc1[j0 + 2], sc1[j0 + 3]};
        float t[4] = {sh1[j0], sh1[j0 + 1], sh1[j0 + 2], sh1[j0 + 3]};
        #pragma unroll
        for (int i = 0; i < 8; ++i)
            #pragma unroll
            for (int j = 0; j < 4; ++j)
                zt[(j0 + j) * ZT_LD + n0 + i] = fmaxf(fmaf(acc[i][j], s[j], t[j]), 0.f);
    }
    const float* w2 = W2 + layer * D * D;
    #pragma unroll
    for (int i = tid; i < D * D; i += 256) Wb[i] = __ldg(w2 + i);
    __syncthreads();

    // ---- Phase 2: y @ W2 ----
    #pragma unroll
    for (int i = 0; i < 8; ++i)
        #pragma unroll
        for (int j = 0; j < 4; ++j) acc[i][j] = 0.f;

    #pragma unroll 4
    for (int k = 0; k < D; ++k) {
        float4 ya = *reinterpret_cast<const float4*>(zt + k * ZT_LD + n0);
        float4 yb = *reinterpret_cast<const float4*>(zt + k * ZT_LD + n0 + 4);
        float4 w  = *reinterpret_cast<const float4*>(Wb + k * D + j0);
        float yr[8] = {ya.x, ya.y, ya.z, ya.w, yb.x, yb.y, yb.z, yb.w};
        #pragma unroll
        for (int i = 0; i < 8; ++i) {
            acc[i][0] = fmaf(yr[i], w.x, acc[i][0]);
            acc[i][1] = fmaf(yr[i], w.y, acc[i][1]);
            acc[i][2] = fmaf(yr[i], w.z, acc[i][2]);
            acc[i][3] = fmaf(yr[i], w.w, acc[i][3]);
        }
    }

    // BN2 + ReLU, coalesced vector store
    {
        float s[4] = {sc2[j0], sc2[j0 + 1], sc2[j0 + 2], sc2[j0 + 3]};
        float t[4] = {sh2[j0], sh2[j0 + 1], sh2[j0 + 2], sh2[j0 + 3]};
        #pragma unroll
        for (int i = 0; i < 8; ++i) {
            int n = node0 + n0 + i;
            if (n < N_NODES) {
                float4 r;
                r.x = fmaxf(fmaf(acc[i][0], s[0], t[0]), 0.f);
                r.y = fmaxf(fmaf(acc[i][1], s[1], t[1]), 0.f);
                r.z = fmaxf(fmaf(acc[i][2], s[2], t[2]), 0.f);
                r.w = fmaxf(fmaf(acc[i][3], s[3], t[3]), 0.f);
                *reinterpret_cast<float4*>(hout + (size_t)n * D + j0) = r;
            }
        }
    }
}

// ---------------- global mean pool (batch is sorted int32) ----------------
#define POOL_BLOCKS 256
__global__ __launch_bounds__(256) void pool_kernel(const int* __restrict__ batch, int sel) {
    const float* __restrict__ h = g_h[sel];
    int d = threadIdx.x & 63;
    int row = blockIdx.x * 4 + (threadIdx.x >> 6);
    int total_rows = POOL_BLOCKS * 4;
    int chunk = (N_NODES + total_rows - 1) / total_rows;
    int start = row * chunk;
    int end = min(start + chunk, N_NODES);
    if (start >= end) return;
    int cur = __ldg(batch + start);
    float acc = 0.f, cnt = 0.f;
    for (int n = start; n < end; ++n) {
        int b = __ldg(batch + n);
        if (b != cur) {
            if ((unsigned)cur < N_GRAPHS) {
                atomicAdd(&g_pool[cur * D + d], acc);
                if (d == 0) atomicAdd(&g_cnt[cur], cnt);
            }
            acc = 0.f; cnt = 0.f; cur = b;
        }
        acc += __ldg(h + (size_t)n * D + d);
        cnt += 1.f;
    }
    if ((unsigned)cur < N_GRAPHS) {
        atomicAdd(&g_pool[cur * D + d], acc);
        if (d == 0) atomicAdd(&g_cnt[cur], cnt);
    }
}

// ---------------- heads: out = [primary(16x6), secondary(16x6)] ----------------
__global__ void head_kernel(const float* __restrict__ wp, const float* __restrict__ bp,
                            const float* __restrict__ ws, const float* __restrict__ bs,
                            float* __restrict__ out) {
    int t = threadIdx.x;
    if (t >= N_GRAPHS * N_CLASSES) return;
    int g = t / N_CLASSES, c = t % N_CLASSES;
    float inv = 1.f / fmaxf(g_cnt[g], 1.f);
    float accP = 0.f, accS = 0.f;
    #pragma unroll
    for (int d = 0; d < D; ++d) {
        float p = g_pool[g * D + d] * inv;
        accP = fmaf(p, wp[d * N_CLASSES + c], accP);
        accS = fmaf(p, ws[d * N_CLASSES + c], accS);
    }
    out[g * N_CLASSES + c] = accP + bp[c];
    out[N_GRAPHS * N_CLASSES + g * N_CLASSES + c] = accS + bs[c];
}

// ---------------- launch ----------------
extern "C" void kernel_launch(void* const* d_in, const int* in_sizes, int n_in,
                              void* d_out, int out_size) {
    const float* x   = (const float*)d_in[0];
    const int*   ei  = (const int*)d_in[1];    // int32 (JAX x64 disabled)
    const int*   bat = (const int*)d_in[2];    // int32
    const float* W1  = (const float*)d_in[3];
    const float* b1  = (const float*)d_in[4];
    const float* g1  = (const float*)d_in[5];
    const float* be1 = (const float*)d_in[6];
    const float* m1  = (const float*)d_in[7];
    const float* v1  = (const float*)d_in[8];
    const float* W2  = (const float*)d_in[9];
    const float* b2  = (const float*)d_in[10];
    const float* g2  = (const float*)d_in[11];
    const float* be2 = (const float*)d_in[12];
    const float* m2  = (const float*)d_in[13];
    const float* v2  = (const float*)d_in[14];
    const float* wp  = (const float*)d_in[15];
    const float* bp  = (const float*)d_in[16];
    const float* ws  = (const float*)d_in[17];
    const float* bs  = (const float*)d_in[18];
    float* out = (float*)d_out;

    const size_t layer_smem = LAYER_SMEM_FLOATS * sizeof(float);  // 51.2 KB
    cudaFuncSetAttribute(layer_kernel, cudaFuncAttributeMaxDynamicSharedMemorySize,
                         (int)layer_smem);

    // CSR build (per call; deterministic work)
    prep_kernel<<<512, 256>>>();
    hist_kernel<<<(N_EDGES + 255) / 256, 256>>>(ei);
    scan_kernel<<<1, 1024>>>();
    place_kernel<<<(N_EDGES + 255) / 256, 256>>>(ei);

    const int layer_grid = (N_NODES + NPB - 1) / NPB;
    layer_kernel<<<layer_grid, 256, layer_smem>>>(x, -1, 0, 0,
        W1, b1, g1, be1, m1, v1, W2, b2, g2, be2, m2, v2);
    layer_kernel<<<layer_grid, 256, layer_smem>>>(x, 0, 1, 1,
        W1, b1, g1, be1, m1, v1, W2, b2, g2, be2, m2, v2);
    layer_kernel<<<layer_grid, 256, layer_smem>>>(x, 1, 0, 2,
        W1, b1, g1, be1, m1, v1, W2, b2, g2, be2, m2, v2);

    pool_kernel<<<POOL_BLOCKS, 256>>>(bat, 0);
    head_kernel<<<1, 128>>>(wp, bp, ws, bs, out);
}